// round 12
// baseline (speedup 1.0000x reference)
#include <cuda_runtime.h>
#include <stdint.h>

// RadarDopSparseProcessor — exact 0.9-quantile: 12-bit radix histogram +
// candidate collect with exact in-smem selection tail; then ordered
// lookback stream compaction. 3 full-cube passes total.

#define Bn 4
#define Zd 40
#define Yd 320
#define Xd 320
#define Nv (Zd*Yd*Xd)            // 4,096,000
#define Kpad (Nv/10 + 64)        // 409,664
#define BKr (Bn*Kpad)            // 1,638,656
#define VPBATCH (Nv/4)           // 1,024,000 float4 per batch

#define HV_BLOCKS 37
#define VPB 27676                // ceil(1024000/37)
#define SC_BLOCKS 250
#define SC_THREADS 512
#define MAXC Nv
#define SENT 0xFFFFFFFFu
#define CFAST 8192               // exact-select threshold (smem capacity)

__device__ unsigned g_hist1[Bn][4096];
__device__ unsigned g_s1[Bn][4];          // binA, remA, binB, remB
__device__ unsigned g_ccnt[Bn];
__device__ unsigned g_cand[Bn][MAXC];
__device__ float    g_thr[Bn];
__device__ unsigned g_done1[Bn];
__device__ unsigned g_done2[Bn];
__device__ unsigned long long g_part[Bn][SC_BLOCKS];
__device__ unsigned g_total[Bn];

__device__ __forceinline__ unsigned wscan(unsigned v, int lane){
  #pragma unroll
  for (int d=1; d<32; d<<=1){
    unsigned n = __shfl_up_sync(0xFFFFFFFFu, v, d);
    if (lane >= d) v += n;
  }
  return v;
}

__device__ __forceinline__ void qranks(unsigned& R0, unsigned& R1){
  const float QPOS = 0.9f * (float)(Nv-1);
  R0 = (unsigned)floorf(QPOS);
  R1 = (unsigned)ceilf(QPOS); if (R1 > Nv-1) R1 = Nv-1;
}

__global__ __launch_bounds__(1024) void k_zero(){
  int i = blockIdx.x*1024 + threadIdx.x;
  if (i < Bn*4096)      (&g_hist1[0][0])[i] = 0u;
  if (i < Bn*SC_BLOCKS) (&g_part[0][0])[i] = 0ull;
  if (i < Bn){ g_done1[i]=0u; g_done2[i]=0u; g_ccnt[i]=0u; g_total[i]=0u; }
}

// ---- block-collective select over a 4096-bin smem histogram (1024 threads) ----
__device__ void bsel4096(const unsigned* h, unsigned rA, unsigned rB,
                         unsigned* swq, unsigned* res){
  int tid=threadIdx.x, lane=tid&31;
  unsigned l0=h[tid*4+0],l1=h[tid*4+1],l2=h[tid*4+2],l3=h[tid*4+3];
  unsigned sum=l0+l1+l2+l3;
  unsigned inc=wscan(sum,lane);
  if (lane==31) swq[tid>>5]=inc;
  __syncthreads();
  if (tid==0){unsigned run=0; for(int k=0;k<32;k++){unsigned t=swq[k];swq[k]=run;run+=t;}}
  __syncthreads();
  unsigned excl=inc-sum+swq[tid>>5];
  unsigned rr[2]={rA,rB};
  #pragma unroll
  for (int j=0;j<2;j++){
    unsigned r=rr[j];
    if (r!=SENT && r>=excl && r<excl+sum){
      unsigned c=excl; unsigned loc[4]={l0,l1,l2,l3};
      #pragma unroll
      for (int k=0;k<4;k++){
        if (r < c+loc[k]){ res[2*j]=(unsigned)(tid*4+k); res[2*j+1]=r-c; break; }
        c+=loc[k];
      }
    }
  }
  __syncthreads();
}

__device__ void bsel256(const unsigned* h, unsigned rA, unsigned rB,
                        unsigned* swq, unsigned* res){
  int tid=threadIdx.x, lane=tid&31;
  unsigned v=0, inc=0;
  if (tid<256){ v=h[tid]; inc=wscan(v,lane); }
  if (tid<256 && lane==31) swq[tid>>5]=inc;
  __syncthreads();
  if (tid==0){unsigned run=0; for(int k=0;k<8;k++){unsigned t=swq[k];swq[k]=run;run+=t;}}
  __syncthreads();
  if (tid<256){
    unsigned excl=inc-v+swq[tid>>5];
    unsigned rr[2]={rA,rB};
    #pragma unroll
    for (int j=0;j<2;j++){
      unsigned r=rr[j];
      if (r!=SENT && r>=excl && r<excl+v) res[2*j]=(unsigned)tid;
    }
  }
  __syncthreads();
}

// ---- last-block detection (threadFenceReduction pattern) ----
__device__ __forceinline__ bool last_block(unsigned* ctr, unsigned total, bool* sflag){
  __threadfence();
  __syncthreads();
  if (threadIdx.x==0) *sflag = (atomicAdd(ctr,1u) == total-1u);
  __syncthreads();
  return *sflag;
}

// ---------------- pass 1: 12-bit histogram, 2-way replicated smem ----------------
__device__ __forceinline__ void h1a(unsigned* h, float4 a){
  atomicAdd(&h[__float_as_uint(a.x)>>20],1u);
  atomicAdd(&h[__float_as_uint(a.y)>>20],1u);
  atomicAdd(&h[__float_as_uint(a.z)>>20],1u);
  atomicAdd(&h[__float_as_uint(a.w)>>20],1u);
}
__global__ __launch_bounds__(1024) void k_hist1(const float* __restrict__ cube){
  __shared__ unsigned hist[2][4096];
  __shared__ unsigned swq[32];
  __shared__ unsigned sres[4];
  __shared__ bool sflag;
  int b = blockIdx.y, tid = threadIdx.x;
  unsigned* myh = hist[(tid>>5)&1];
  int start = blockIdx.x * VPB;
  int n = min(VPB, VPBATCH - start);
  const float4* p = (const float4*)cube + (size_t)b*VPBATCH + start;
  for (int i=tid;i<8192;i+=1024) (&hist[0][0])[i]=0u;
  __syncthreads();
  int i = tid;
  for (; i + 3072 < n; i += 4096){
    float4 v0=p[i], v1=p[i+1024], v2=p[i+2048], v3=p[i+3072];
    h1a(myh,v0); h1a(myh,v1); h1a(myh,v2); h1a(myh,v3);
  }
  for (; i < n; i += 1024) h1a(myh, p[i]);
  __syncthreads();
  for (int k=tid;k<4096;k+=1024){
    unsigned c=hist[0][k]+hist[1][k];
    if (c) atomicAdd(&g_hist1[b][k], c);
  }
  // tail: last block per batch computes select1
  if (last_block(&g_done1[b], HV_BLOCKS, &sflag)){
    for (int k=tid;k<4096;k+=1024) hist[0][k]=__ldcg(&g_hist1[b][k]);
    __syncthreads();
    unsigned R0,R1; qranks(R0,R1);
    bsel4096(hist[0], R0, R1, swq, sres);
    if (tid<4) g_s1[b][tid]=sres[tid];
  }
}

// ---------------- pass 2: candidate collect + exact selection tail ----------------
__global__ __launch_bounds__(1024) void k_collect(const float* __restrict__ cube){
  __shared__ unsigned sc[CFAST];     // 32 KB: candidate cache / fallback hist
  __shared__ unsigned swq[32];
  __shared__ unsigned sres[4];
  __shared__ bool sflag;
  __shared__ float sval[2];
  int b=blockIdx.y, tid=threadIdx.x;

  unsigned binA=__ldcg(&g_s1[b][0]);
  unsigned binB=__ldcg(&g_s1[b][2]);

  int start = blockIdx.x*VPB;
  int n = min(VPB, VPBATCH - start);
  const float4* p=(const float4*)cube + (size_t)b*VPBATCH + start;
  int i = tid;
  for (; i + 3072 < n; i += 4096){
    float4 v0=p[i], v1=p[i+1024], v2=p[i+2048], v3=p[i+3072];
    float vv[16]={v0.x,v0.y,v0.z,v0.w, v1.x,v1.y,v1.z,v1.w,
                  v2.x,v2.y,v2.z,v2.w, v3.x,v3.y,v3.z,v3.w};
    #pragma unroll
    for (int k=0;k<16;k++){
      unsigned u=__float_as_uint(vv[k]); unsigned t=u>>20;
      if (t==binA || t==binB) g_cand[b][atomicAdd(&g_ccnt[b],1u)]=u;
    }
  }
  for (; i < n; i += 1024){
    float4 a=p[i];
    float vv[4]={a.x,a.y,a.z,a.w};
    #pragma unroll
    for (int k=0;k<4;k++){
      unsigned u=__float_as_uint(vv[k]); unsigned t=u>>20;
      if (t==binA || t==binB) g_cand[b][atomicAdd(&g_ccnt[b],1u)]=u;
    }
  }

  // tail: last block per batch does exact selection over candidates
  if (last_block(&g_done2[b], HV_BLOCKS, &sflag)){
    unsigned remA=__ldcg(&g_s1[b][1]);
    unsigned remB=__ldcg(&g_s1[b][3]);
    unsigned cc = __ldcg(&g_ccnt[b]);
    const float QPOS = 0.9f * (float)(Nv-1);
    float frac = QPOS - floorf(QPOS);

    if (cc <= CFAST){
      // ---- fast path: exact rank-by-counting in smem ----
      for (unsigned k=tid;k<cc;k+=1024) sc[k]=__ldcg(&g_cand[b][k]);
      __syncthreads();
      // target j=0: rank remA among candidates with prefix binA
      // target j=1: rank remB among candidates with prefix binB
      unsigned tgtbin[2]={binA,binB};
      unsigned tgtrem[2]={remA,remB};
      #pragma unroll
      for (int j=0;j<2;j++){
        unsigned tb=tgtbin[j], tr=tgtrem[j];
        for (unsigned k=tid;k<cc;k+=1024){
          unsigned v=sc[k];
          if ((v>>20)==tb){
            unsigned less=0, eq=0;
            for (unsigned m=0;m<cc;m++){
              unsigned w=sc[m];
              if ((w>>20)==tb){
                less += (w < v);
                eq   += (w == v);
              }
            }
            if (tr >= less && tr < less+eq) sval[j]=__uint_as_float(v);
          }
        }
      }
      __syncthreads();
    } else {
      // ---- fallback (adversarial): two-level radix over global candidates ----
      unsigned sel2A, rem2A, sel2B, rem2B;
      // level 2: bits [19:8], two 4096-bin hists (A in sc[0:4096], B in sc[4096:8192])
      for (int k=tid;k<8192;k+=1024) sc[k]=0u;
      __syncthreads();
      for (unsigned base=0; base<cc; base+=8192u){
        unsigned u[8]; bool m[8];
        #pragma unroll
        for (int j=0;j<8;j++){
          unsigned idx = base + (unsigned)j*1024u + (unsigned)tid;
          m[j] = (idx < cc);
          u[j] = m[j] ? __ldcg(&g_cand[b][idx]) : 0u;
        }
        #pragma unroll
        for (int j=0;j<8;j++){
          if (m[j]){
            unsigned t=u[j]>>20;
            if (t==binA) atomicAdd(&sc[(u[j]>>8)&0xFFFu],1u);
            else if (t==binB) atomicAdd(&sc[4096u+((u[j]>>8)&0xFFFu)],1u);
          }
        }
      }
      __syncthreads();
      if (binA==binB){
        bsel4096(&sc[0], remA, remB, swq, sres);
        sel2A=(binA<<12)|sres[0]; rem2A=sres[1];
        sel2B=(binB<<12)|sres[2]; rem2B=sres[3];
      } else {
        bsel4096(&sc[0], remA, SENT, swq, sres);
        sel2A=(binA<<12)|sres[0]; rem2A=sres[1];
        bsel4096(&sc[4096], SENT, remB, swq, sres);
        sel2B=(binB<<12)|sres[2]; rem2B=sres[3];
      }
      __syncthreads();
      // level 3: bits [7:0], two 256-bin hists
      for (int k=tid;k<512;k+=1024) sc[k]=0u;
      __syncthreads();
      for (unsigned base=0; base<cc; base+=8192u){
        unsigned u[8]; bool m[8];
        #pragma unroll
        for (int j=0;j<8;j++){
          unsigned idx = base + (unsigned)j*1024u + (unsigned)tid;
          m[j] = (idx < cc);
          u[j] = m[j] ? __ldcg(&g_cand[b][idx]) : 0u;
        }
        #pragma unroll
        for (int j=0;j<8;j++){
          if (m[j]){
            unsigned pre=u[j]>>8;
            if (pre==sel2A) atomicAdd(&sc[u[j]&0xFFu],1u);
            else if (pre==sel2B) atomicAdd(&sc[256u+(u[j]&0xFFu)],1u);
          }
        }
      }
      __syncthreads();
      unsigned bA, bB;
      if (sel2A==sel2B){
        bsel256(&sc[0], rem2A, rem2B, swq, sres);
        bA=sres[0]; bB=sres[2];
      } else {
        bsel256(&sc[0], rem2A, SENT, swq, sres);
        bA=sres[0];
        __syncthreads();
        bsel256(&sc[256], SENT, rem2B, swq, sres);
        bB=sres[2];
      }
      if (tid==0){
        sval[0]=__uint_as_float((sel2A<<8)|bA);
        sval[1]=__uint_as_float((sel2B<<8)|bB);
      }
      __syncthreads();
    }
    if (tid==0) g_thr[b] = sval[0]*(1.0f-frac) + sval[1]*frac;
  }
}

// ---------------- fused compaction with decoupled lookback (R11-passing) ----------------
__global__ __launch_bounds__(SC_THREADS) void k_scatter(const float* __restrict__ cube,
                                                        const float* __restrict__ dop,
                                                        float* __restrict__ out, int out_elems){
  __shared__ unsigned warpsum[16];
  __shared__ unsigned warpexcl[16];
  __shared__ unsigned s_agg;
  __shared__ unsigned s_gexcl;
  int b = blockIdx.y;
  float thr = g_thr[b];
  int tid = threadIdx.x, lane = tid & 31, wid = tid >> 5;

  unsigned gvec0 = (unsigned)blockIdx.x*4096u + (unsigned)wid*256u;
  const float4* p = (const float4*)cube + (size_t)b*VPBATCH + gvec0;

  float4 v[8];
  #pragma unroll
  for (int j=0;j<8;j++) v[j] = p[j*32 + lane];

  unsigned esc[8], gbase[8];
  unsigned run = 0;
  #pragma unroll
  for (int j=0;j<8;j++){
    unsigned c = (v[j].x>thr)+(v[j].y>thr)+(v[j].z>thr)+(v[j].w>thr);
    unsigned inc = c;
    #pragma unroll
    for (int d=1;d<32;d<<=1){ unsigned t=__shfl_up_sync(0xFFFFFFFFu,inc,d); if (lane>=d) inc+=t; }
    esc[j] = inc - c;
    gbase[j] = run;
    run += __shfl_sync(0xFFFFFFFFu, inc, 31);
  }
  if (lane==0) warpsum[wid] = run;
  __syncthreads();
  if (tid==0){
    unsigned acc=0;
    for (int k=0;k<16;k++){ unsigned t=warpsum[k]; warpexcl[k]=acc; acc+=t; }
    s_agg = acc;
  }
  __syncthreads();

  if (wid==0){
    unsigned agg = s_agg;
    unsigned excl = 0;
    int bx = blockIdx.x;
    if (bx == 0){
      if (lane==0) atomicExch(&g_part[b][0], (2ull<<62) | (unsigned long long)agg);
    } else {
      if (lane==0) atomicExch(&g_part[b][bx], (1ull<<62) | (unsigned long long)agg);
      unsigned running = 0;
      int j = bx - 1;
      while (true){
        int idx = j - lane;
        unsigned long long w; unsigned st;
        do {
          w = (idx >= 0) ? atomicAdd(&g_part[b][idx], 0ull) : (2ull<<62);
          st = (unsigned)(w>>62);
        } while (__any_sync(0xFFFFFFFFu, st==0u));
        unsigned val = (unsigned)(w & 0xFFFFFFFFull);
        unsigned bal = __ballot_sync(0xFFFFFFFFu, st==2u);
        if (bal){
          int f = __ffs(bal)-1;
          unsigned contrib = (lane<=f) ? val : 0u;
          #pragma unroll
          for (int d=16;d>0;d>>=1) contrib += __shfl_down_sync(0xFFFFFFFFu,contrib,d);
          running += __shfl_sync(0xFFFFFFFFu, contrib, 0);
          break;
        } else {
          unsigned contrib = val;
          #pragma unroll
          for (int d=16;d>0;d>>=1) contrib += __shfl_down_sync(0xFFFFFFFFu,contrib,d);
          running += __shfl_sync(0xFFFFFFFFu, contrib, 0);
          j -= 32;
        }
      }
      excl = running;
      if (lane==0) atomicExch(&g_part[b][bx], (2ull<<62) | (unsigned long long)(excl+agg));
    }
    if (lane==0){
      s_gexcl = excl;
      if (bx == SC_BLOCKS-1) g_total[b] = excl + agg;
    }
  }
  __syncthreads();

  unsigned warpbase = s_gexcl + warpexcl[wid];
  const float* dopb = dop + (size_t)b*Nv;
  #pragma unroll
  for (int j=0;j<8;j++){
    unsigned o = warpbase + gbase[j] + esc[j];
    unsigned gvec = gvec0 + (unsigned)j*32u + (unsigned)lane;
    float vals[4] = {v[j].x, v[j].y, v[j].z, v[j].w};
    #pragma unroll
    for (int c2=0;c2<4;c2++){
      if (vals[c2] > thr){
        unsigned gidx = gvec*4u + (unsigned)c2;
        unsigned z = gidx/(Yd*Xd);
        unsigned rem = gidx - z*(Yd*Xd);
        unsigned y = rem/Xd;
        unsigned x = rem - y*Xd;
        unsigned row = (unsigned)b*Kpad + o;
        float dv = dopb[gidx];
        size_t f = (size_t)row*5;
        if (f + 5 <= (size_t)out_elems){
          out[f+0] = ((float)x/320.0f)*72.0f;
          out[f+1] = ((float)y/320.0f)*32.0f;
          out[f+2] = ((float)z/40.0f)*8.0f;
          out[f+3] = vals[c2] / 10000000000000.0f;
          out[f+4] = dv - 1.9326f;
        }
        size_t ioff = (size_t)BKr*5 + (size_t)row*4;
        if (ioff + 4 <= (size_t)out_elems){
          out[ioff+0]=(float)b; out[ioff+1]=(float)z;
          out[ioff+2]=(float)y; out[ioff+3]=(float)x;
        }
        size_t voff = (size_t)BKr*9 + (size_t)row;
        if (voff < (size_t)out_elems) out[voff] = 1.0f;
        o++;
      }
    }
  }
}

// ---------------- zero only the invalid tail rows ----------------
__global__ __launch_bounds__(256) void k_cleanup(float* __restrict__ out, int out_elems){
  unsigned row = blockIdx.x*256u + threadIdx.x;
  if (row >= (unsigned)BKr) return;
  unsigned b = row / Kpad;
  unsigned r = row - b*Kpad;
  if (r < __ldcg(&g_total[b])) return;
  size_t f = (size_t)row*5;
  if (f + 5 <= (size_t)out_elems){
    out[f+0]=0.f; out[f+1]=0.f; out[f+2]=0.f; out[f+3]=0.f; out[f+4]=0.f;
  }
  size_t ioff = (size_t)BKr*5 + (size_t)row*4;
  if (ioff + 4 <= (size_t)out_elems){
    out[ioff+0]=0.f; out[ioff+1]=0.f; out[ioff+2]=0.f; out[ioff+3]=0.f;
  }
  size_t voff = (size_t)BKr*9 + (size_t)row;
  if (voff < (size_t)out_elems) out[voff] = 0.f;
}

extern "C" void kernel_launch(void* const* d_in, const int* in_sizes, int n_in,
                              void* d_out, int out_size) {
  const float* cube = (const float*)d_in[0];
  const float* dop  = (const float*)d_in[1];
  float* out = (float*)d_out;

  if ((size_t)out_size > (size_t)BKr*10)
    cudaMemsetAsync(out + (size_t)BKr*10, 0,
                    ((size_t)out_size - (size_t)BKr*10)*sizeof(float));

  k_zero<<<32,1024>>>();

  dim3 gh(HV_BLOCKS, Bn);
  k_hist1<<<gh,1024>>>(cube);
  k_collect<<<gh,1024>>>(cube);

  dim3 gs(SC_BLOCKS, Bn);
  k_scatter<<<gs,SC_THREADS>>>(cube, dop, out, out_size);
  k_cleanup<<<(BKr+255)/256,256>>>(out, out_size);
}

// round 13
// speedup vs baseline: 3.5254x; 3.5254x over previous
#include <cuda_runtime.h>
#include <stdint.h>

// RadarDopSparseProcessor — exact 0.9-quantile radix select (12b/12b/8b full
// passes, select computed in each pass's last-block tail) + ordered lookback
// stream compaction.

#define Bn 4
#define Zd 40
#define Yd 320
#define Xd 320
#define Nv (Zd*Yd*Xd)            // 4,096,000
#define Kpad (Nv/10 + 64)        // 409,664
#define BKr (Bn*Kpad)            // 1,638,656
#define VPBATCH (Nv/4)           // 1,024,000 float4 per batch

#define HV_BLOCKS 37
#define VPB 27676                // ceil(1024000/37)
#define SC_BLOCKS 250
#define SC_THREADS 512
#define SENT 0xFFFFFFFFu

__device__ unsigned g_hist1[Bn][4096];
__device__ unsigned g_hist2[Bn][2][4096];
__device__ unsigned g_hist3[Bn][2][256];
__device__ unsigned g_s1[Bn][4];          // selA, remA, selB, remB
__device__ unsigned g_s2[Bn][4];          // sel2A, rem2A, sel2B, rem2B
__device__ float    g_thr[Bn];
__device__ unsigned g_done1[Bn];
__device__ unsigned g_done2[Bn];
__device__ unsigned g_done3[Bn];
__device__ unsigned long long g_part[Bn][SC_BLOCKS];
__device__ unsigned g_total[Bn];

__device__ __forceinline__ unsigned wscan(unsigned v, int lane){
  #pragma unroll
  for (int d=1; d<32; d<<=1){
    unsigned n = __shfl_up_sync(0xFFFFFFFFu, v, d);
    if (lane >= d) v += n;
  }
  return v;
}

__device__ __forceinline__ void qranks(unsigned& R0, unsigned& R1){
  const float QPOS = 0.9f * (float)(Nv-1);
  R0 = (unsigned)floorf(QPOS);
  R1 = (unsigned)ceilf(QPOS); if (R1 > Nv-1) R1 = Nv-1;
}

__global__ __launch_bounds__(1024) void k_zero(){
  int i = blockIdx.x*1024 + threadIdx.x;
  if (i < Bn*4096)      (&g_hist1[0][0])[i] = 0u;
  if (i < Bn*2*4096)    (&g_hist2[0][0][0])[i] = 0u;
  if (i < Bn*2*256)     (&g_hist3[0][0][0])[i] = 0u;
  if (i < Bn*SC_BLOCKS) (&g_part[0][0])[i] = 0ull;
  if (i < Bn){ g_done1[i]=0u; g_done2[i]=0u; g_done3[i]=0u; g_total[i]=0u; }
}

// ---- block-collective select over a 4096-bin smem histogram (1024 threads) ----
__device__ void bsel4096(const unsigned* h, unsigned rA, unsigned rB,
                         unsigned* swq, unsigned* res){
  int tid=threadIdx.x, lane=tid&31;
  unsigned l0=h[tid*4+0],l1=h[tid*4+1],l2=h[tid*4+2],l3=h[tid*4+3];
  unsigned sum=l0+l1+l2+l3;
  unsigned inc=wscan(sum,lane);
  if (lane==31) swq[tid>>5]=inc;
  __syncthreads();
  if (tid==0){unsigned run=0; for(int k=0;k<32;k++){unsigned t=swq[k];swq[k]=run;run+=t;}}
  __syncthreads();
  unsigned excl=inc-sum+swq[tid>>5];
  unsigned rr[2]={rA,rB};
  #pragma unroll
  for (int j=0;j<2;j++){
    unsigned r=rr[j];
    if (r!=SENT && r>=excl && r<excl+sum){
      unsigned c=excl; unsigned loc[4]={l0,l1,l2,l3};
      #pragma unroll
      for (int k=0;k<4;k++){
        if (r < c+loc[k]){ res[2*j]=(unsigned)(tid*4+k); res[2*j+1]=r-c; break; }
        c+=loc[k];
      }
    }
  }
  __syncthreads();
}

__device__ void bsel256(const unsigned* h, unsigned rA, unsigned rB,
                        unsigned* swq, unsigned* res){
  int tid=threadIdx.x, lane=tid&31;
  unsigned v=0, inc=0;
  if (tid<256){ v=h[tid]; inc=wscan(v,lane); }
  if (tid<256 && lane==31) swq[tid>>5]=inc;
  __syncthreads();
  if (tid==0){unsigned run=0; for(int k=0;k<8;k++){unsigned t=swq[k];swq[k]=run;run+=t;}}
  __syncthreads();
  if (tid<256){
    unsigned excl=inc-v+swq[tid>>5];
    unsigned rr[2]={rA,rB};
    #pragma unroll
    for (int j=0;j<2;j++){
      unsigned r=rr[j];
      if (r!=SENT && r>=excl && r<excl+v) res[2*j]=(unsigned)tid;
    }
  }
  __syncthreads();
}

// ---- last-block detection (threadFenceReduction pattern) ----
__device__ __forceinline__ bool last_block(unsigned* ctr, unsigned total, bool* sflag){
  __threadfence();
  __syncthreads();
  if (threadIdx.x==0) *sflag = (atomicAdd(ctr,1u) == total-1u);
  __syncthreads();
  return *sflag;
}

// ---------------- pass 1: 12-bit histogram, 2-way replicated smem ----------------
__device__ __forceinline__ void h1a(unsigned* h, float4 a){
  atomicAdd(&h[__float_as_uint(a.x)>>20],1u);
  atomicAdd(&h[__float_as_uint(a.y)>>20],1u);
  atomicAdd(&h[__float_as_uint(a.z)>>20],1u);
  atomicAdd(&h[__float_as_uint(a.w)>>20],1u);
}
__global__ __launch_bounds__(1024) void k_hist1(const float* __restrict__ cube){
  __shared__ unsigned hist[2][4096];
  __shared__ unsigned swq[32];
  __shared__ unsigned sres[4];
  __shared__ bool sflag;
  int b = blockIdx.y, tid = threadIdx.x;
  unsigned* myh = hist[(tid>>5)&1];
  int start = blockIdx.x * VPB;
  int n = min(VPB, VPBATCH - start);
  const float4* p = (const float4*)cube + (size_t)b*VPBATCH + start;
  for (int i=tid;i<8192;i+=1024) (&hist[0][0])[i]=0u;
  __syncthreads();
  int i = tid;
  for (; i + 3072 < n; i += 4096){
    float4 v0=p[i], v1=p[i+1024], v2=p[i+2048], v3=p[i+3072];
    h1a(myh,v0); h1a(myh,v1); h1a(myh,v2); h1a(myh,v3);
  }
  for (; i < n; i += 1024) h1a(myh, p[i]);
  __syncthreads();
  for (int k=tid;k<4096;k+=1024){
    unsigned c=hist[0][k]+hist[1][k];
    if (c) atomicAdd(&g_hist1[b][k], c);
  }
  if (last_block(&g_done1[b], HV_BLOCKS, &sflag)){
    for (int k=tid;k<4096;k+=1024) hist[0][k]=__ldcg(&g_hist1[b][k]);
    __syncthreads();
    unsigned R0,R1; qranks(R0,R1);
    bsel4096(hist[0], R0, R1, swq, sres);
    if (tid<4) g_s1[b][tid]=sres[tid];
  }
}

// ---------------- pass 2: 12-bit mid histogram (bits 19..8), batched loads ----------------
__device__ __forceinline__ void h2a(unsigned* h0, unsigned* h1, unsigned sa, unsigned sb, float4 a){
  float vv[4]={a.x,a.y,a.z,a.w};
  #pragma unroll
  for (int c2=0;c2<4;c2++){
    unsigned u=__float_as_uint(vv[c2]); unsigned t=u>>20;
    if (t==sa) atomicAdd(&h0[(u>>8)&0xFFFu],1u);
    else if (t==sb) atomicAdd(&h1[(u>>8)&0xFFFu],1u);
  }
}
__global__ __launch_bounds__(1024) void k_hist2(const float* __restrict__ cube){
  __shared__ unsigned hist[2][4096];
  __shared__ unsigned swq[32];
  __shared__ unsigned sres[4];
  __shared__ bool sflag;
  int b = blockIdx.y, tid = threadIdx.x;
  unsigned sa=__ldcg(&g_s1[b][0]);
  unsigned sb=__ldcg(&g_s1[b][2]);
  for (int i=tid;i<8192;i+=1024) (&hist[0][0])[i]=0u;
  __syncthreads();
  int start = blockIdx.x * VPB;
  int n = min(VPB, VPBATCH - start);
  const float4* p = (const float4*)cube + (size_t)b*VPBATCH + start;
  int i = tid;
  for (; i + 3072 < n; i += 4096){
    float4 v0=p[i], v1=p[i+1024], v2=p[i+2048], v3=p[i+3072];
    h2a(hist[0],hist[1],sa,sb,v0); h2a(hist[0],hist[1],sa,sb,v1);
    h2a(hist[0],hist[1],sa,sb,v2); h2a(hist[0],hist[1],sa,sb,v3);
  }
  for (; i < n; i += 1024) h2a(hist[0],hist[1],sa,sb,p[i]);
  __syncthreads();
  for (int k=tid;k<8192;k+=1024){
    unsigned c=(&hist[0][0])[k];
    if (c) atomicAdd((&g_hist2[b][0][0])+k, c);
  }
  if (last_block(&g_done2[b], HV_BLOCKS, &sflag)){
    unsigned selA=__ldcg(&g_s1[b][0]), remA=__ldcg(&g_s1[b][1]);
    unsigned selB=__ldcg(&g_s1[b][2]), remB=__ldcg(&g_s1[b][3]);
    unsigned sel2A, rem2A, sel2B, rem2B;
    for (int k=tid;k<4096;k+=1024) hist[0][k]=__ldcg(&g_hist2[b][0][k]);
    __syncthreads();
    if (selA==selB){
      bsel4096(hist[0], remA, remB, swq, sres);
      sel2A=(selA<<12)|sres[0]; rem2A=sres[1];
      sel2B=(selB<<12)|sres[2]; rem2B=sres[3];
    } else {
      bsel4096(hist[0], remA, SENT, swq, sres);
      sel2A=(selA<<12)|sres[0]; rem2A=sres[1];
      __syncthreads();
      for (int k=tid;k<4096;k+=1024) hist[0][k]=__ldcg(&g_hist2[b][1][k]);
      __syncthreads();
      bsel4096(hist[0], SENT, remB, swq, sres);
      sel2B=(selB<<12)|sres[2]; rem2B=sres[3];
    }
    if (tid==0){ g_s2[b][0]=sel2A; g_s2[b][1]=rem2A; g_s2[b][2]=sel2B; g_s2[b][3]=rem2B; }
  }
}

// ---------------- pass 3: 8-bit histogram (bits 7..0), batched loads ----------------
__device__ __forceinline__ void h3a(unsigned* h8, unsigned p0, unsigned p1, float4 a){
  float vv[4]={a.x,a.y,a.z,a.w};
  #pragma unroll
  for (int c2=0;c2<4;c2++){
    unsigned u=__float_as_uint(vv[c2]); unsigned pre=u>>8;
    if (pre==p0) atomicAdd(&h8[u&0xFFu],1u);
    else if (pre==p1) atomicAdd(&h8[256u+(u&0xFFu)],1u);
  }
}
__global__ __launch_bounds__(1024) void k_hist3(const float* __restrict__ cube){
  __shared__ unsigned h8[512];
  __shared__ unsigned swq[32];
  __shared__ unsigned sres[4];
  __shared__ bool sflag;
  int b = blockIdx.y, tid = threadIdx.x;
  unsigned p0=__ldcg(&g_s2[b][0]);
  unsigned p1=__ldcg(&g_s2[b][2]);
  for (int i=tid;i<512;i+=1024) h8[i]=0u;
  __syncthreads();
  int start = blockIdx.x * VPB;
  int n = min(VPB, VPBATCH - start);
  const float4* p = (const float4*)cube + (size_t)b*VPBATCH + start;
  int i = tid;
  for (; i + 3072 < n; i += 4096){
    float4 v0=p[i], v1=p[i+1024], v2=p[i+2048], v3=p[i+3072];
    h3a(h8,p0,p1,v0); h3a(h8,p0,p1,v1); h3a(h8,p0,p1,v2); h3a(h8,p0,p1,v3);
  }
  for (; i < n; i += 1024) h3a(h8,p0,p1,p[i]);
  __syncthreads();
  for (int k=tid;k<512;k+=1024){
    unsigned c=h8[k];
    if (c) atomicAdd((&g_hist3[b][0][0])+k, c);
  }
  if (last_block(&g_done3[b], HV_BLOCKS, &sflag)){
    unsigned sel2A=__ldcg(&g_s2[b][0]), rem2A=__ldcg(&g_s2[b][1]);
    unsigned sel2B=__ldcg(&g_s2[b][2]), rem2B=__ldcg(&g_s2[b][3]);
    for (int k=tid;k<512;k+=1024) h8[k]=__ldcg((&g_hist3[b][0][0])+k);
    __syncthreads();
    unsigned binA, binB;
    if (sel2A==sel2B){
      bsel256(&h8[0], rem2A, rem2B, swq, sres);
      binA=sres[0]; binB=sres[2];
    } else {
      bsel256(&h8[0], rem2A, SENT, swq, sres);
      binA=sres[0];
      __syncthreads();
      bsel256(&h8[256], SENT, rem2B, swq, sres);
      binB=sres[2];
    }
    if (tid==0){
      const float QPOS = 0.9f * (float)(Nv-1);
      float frac = QPOS - floorf(QPOS);
      float va=__uint_as_float((sel2A<<8)|binA);
      float vb=__uint_as_float((sel2B<<8)|binB);
      g_thr[b]=va*(1.0f-frac)+vb*frac;
    }
  }
}

// ---------------- fused compaction with decoupled lookback ----------------
__global__ __launch_bounds__(SC_THREADS) void k_scatter(const float* __restrict__ cube,
                                                        const float* __restrict__ dop,
                                                        float* __restrict__ out, int out_elems){
  __shared__ unsigned warpsum[16];
  __shared__ unsigned warpexcl[16];
  __shared__ unsigned s_agg;
  __shared__ unsigned s_gexcl;
  int b = blockIdx.y;
  float thr = g_thr[b];
  int tid = threadIdx.x, lane = tid & 31, wid = tid >> 5;

  unsigned gvec0 = (unsigned)blockIdx.x*4096u + (unsigned)wid*256u;
  const float4* p = (const float4*)cube + (size_t)b*VPBATCH + gvec0;

  float4 v[8];
  #pragma unroll
  for (int j=0;j<8;j++) v[j] = p[j*32 + lane];

  unsigned esc[8], gbase[8];
  unsigned run = 0;
  #pragma unroll
  for (int j=0;j<8;j++){
    unsigned c = (v[j].x>thr)+(v[j].y>thr)+(v[j].z>thr)+(v[j].w>thr);
    unsigned inc = c;
    #pragma unroll
    for (int d=1;d<32;d<<=1){ unsigned t=__shfl_up_sync(0xFFFFFFFFu,inc,d); if (lane>=d) inc+=t; }
    esc[j] = inc - c;
    gbase[j] = run;
    run += __shfl_sync(0xFFFFFFFFu, inc, 31);
  }
  if (lane==0) warpsum[wid] = run;
  __syncthreads();
  if (tid==0){
    unsigned acc=0;
    for (int k=0;k<16;k++){ unsigned t=warpsum[k]; warpexcl[k]=acc; acc+=t; }
    s_agg = acc;
  }
  __syncthreads();

  if (wid==0){
    unsigned agg = s_agg;
    unsigned excl = 0;
    int bx = blockIdx.x;
    if (bx == 0){
      if (lane==0) atomicExch(&g_part[b][0], (2ull<<62) | (unsigned long long)agg);
    } else {
      if (lane==0) atomicExch(&g_part[b][bx], (1ull<<62) | (unsigned long long)agg);
      unsigned running = 0;
      int j = bx - 1;
      while (true){
        int idx = j - lane;
        unsigned long long w; unsigned st;
        do {
          w = (idx >= 0) ? atomicAdd(&g_part[b][idx], 0ull) : (2ull<<62);
          st = (unsigned)(w>>62);
        } while (__any_sync(0xFFFFFFFFu, st==0u));
        unsigned val = (unsigned)(w & 0xFFFFFFFFull);
        unsigned bal = __ballot_sync(0xFFFFFFFFu, st==2u);
        if (bal){
          int f = __ffs(bal)-1;
          unsigned contrib = (lane<=f) ? val : 0u;
          #pragma unroll
          for (int d=16;d>0;d>>=1) contrib += __shfl_down_sync(0xFFFFFFFFu,contrib,d);
          running += __shfl_sync(0xFFFFFFFFu, contrib, 0);
          break;
        } else {
          unsigned contrib = val;
          #pragma unroll
          for (int d=16;d>0;d>>=1) contrib += __shfl_down_sync(0xFFFFFFFFu,contrib,d);
          running += __shfl_sync(0xFFFFFFFFu, contrib, 0);
          j -= 32;
        }
      }
      excl = running;
      if (lane==0) atomicExch(&g_part[b][bx], (2ull<<62) | (unsigned long long)(excl+agg));
    }
    if (lane==0){
      s_gexcl = excl;
      if (bx == SC_BLOCKS-1) g_total[b] = excl + agg;
    }
  }
  __syncthreads();

  unsigned warpbase = s_gexcl + warpexcl[wid];
  const float* dopb = dop + (size_t)b*Nv;
  const bool fits = (out_elems >= (int)(10u*(unsigned)BKr));
  #pragma unroll
  for (int j=0;j<8;j++){
    unsigned o = warpbase + gbase[j] + esc[j];
    unsigned gvec = gvec0 + (unsigned)j*32u + (unsigned)lane;
    float vals[4] = {v[j].x, v[j].y, v[j].z, v[j].w};
    // prefetch doppler for matches (MLP=4)
    float dv[4];
    #pragma unroll
    for (int c2=0;c2<4;c2++){
      if (vals[c2] > thr) dv[c2] = __ldg(&dopb[gvec*4u + (unsigned)c2]);
    }
    #pragma unroll
    for (int c2=0;c2<4;c2++){
      if (vals[c2] > thr){
        unsigned gidx = gvec*4u + (unsigned)c2;
        unsigned z = gidx/(Yd*Xd);
        unsigned rem = gidx - z*(Yd*Xd);
        unsigned y = rem/Xd;
        unsigned x = rem - y*Xd;
        unsigned row = (unsigned)b*Kpad + o;
        if (fits){
          unsigned f = row*5u;
          out[f+0u] = ((float)x/320.0f)*72.0f;
          out[f+1u] = ((float)y/320.0f)*32.0f;
          out[f+2u] = ((float)z/40.0f)*8.0f;
          out[f+3u] = vals[c2] / 10000000000000.0f;
          out[f+4u] = dv[c2] - 1.9326f;
          unsigned ioff = 5u*(unsigned)BKr + row*4u;
          float4 iv = make_float4((float)b,(float)z,(float)y,(float)x);
          *reinterpret_cast<float4*>(out + ioff) = iv;   // 16B-aligned
          out[9u*(unsigned)BKr + row] = 1.0f;
        }
        o++;
      }
    }
  }
}

// ---------------- zero only the invalid tail rows ----------------
__global__ __launch_bounds__(256) void k_cleanup(float* __restrict__ out, int out_elems){
  unsigned row = blockIdx.x*256u + threadIdx.x;
  if (row >= (unsigned)BKr) return;
  unsigned b = row / Kpad;
  unsigned r = row - b*Kpad;
  if (r < __ldcg(&g_total[b])) return;
  const bool fits = (out_elems >= (int)(10u*(unsigned)BKr));
  if (fits){
    unsigned f = row*5u;
    out[f+0u]=0.f; out[f+1u]=0.f; out[f+2u]=0.f; out[f+3u]=0.f; out[f+4u]=0.f;
    unsigned ioff = 5u*(unsigned)BKr + row*4u;
    *reinterpret_cast<float4*>(out + ioff) = make_float4(0.f,0.f,0.f,0.f);
    out[9u*(unsigned)BKr + row] = 0.f;
  }
}

extern "C" void kernel_launch(void* const* d_in, const int* in_sizes, int n_in,
                              void* d_out, int out_size) {
  const float* cube = (const float*)d_in[0];
  const float* dop  = (const float*)d_in[1];
  float* out = (float*)d_out;

  if ((size_t)out_size > (size_t)BKr*10)
    cudaMemsetAsync(out + (size_t)BKr*10, 0,
                    ((size_t)out_size - (size_t)BKr*10)*sizeof(float));
  else if ((size_t)out_size < (size_t)BKr*10)
    cudaMemsetAsync(out, 0, (size_t)out_size * sizeof(float)); // defensive: layout mismatch

  k_zero<<<32,1024>>>();

  dim3 gh(HV_BLOCKS, Bn);
  k_hist1<<<gh,1024>>>(cube);
  k_hist2<<<gh,1024>>>(cube);
  k_hist3<<<gh,1024>>>(cube);

  dim3 gs(SC_BLOCKS, Bn);
  k_scatter<<<gs,SC_THREADS>>>(cube, dop, out, out_size);
  k_cleanup<<<(BKr+255)/256,256>>>(out, out_size);
}